// round 10
// baseline (speedup 1.0000x reference)
#include <cuda_runtime.h>

#define KTAGS 48
#define TLEN 1024
#define STOPID 47
#define NEGV (-10000.0f)

__device__ __forceinline__ unsigned long long pk2(float lo, float hi) {
    unsigned long long r;
    asm("mov.b64 %0, {%1, %2};" : "=l"(r) : "f"(lo), "f"(hi));
    return r;
}
__device__ __forceinline__ void upk2(unsigned long long v, float& lo, float& hi) {
    asm("mov.b64 {%0, %1}, %2;" : "=f"(lo), "=f"(hi) : "l"(v));
}
// d = a*b + d  (packed f32x2 -> SASS FFMA2)
__device__ __forceinline__ void fma2(unsigned long long& d, unsigned long long a, unsigned long long b) {
    asm("fma.rn.f32x2 %0, %1, %2, %0;" : "+l"(d) : "l"(a), "l"(b));
}
__device__ __forceinline__ void add2(unsigned long long& d, unsigned long long a) {
    asm("add.rn.f32x2 %0, %0, %1;" : "+l"(d) : "l"(a));
}

// One block = 4 batches, 8 warps. Warp w: batch blk*4 + (w>>1), fwd if (w&1)==0.
// Warp->SMSP map (wid%4) covers all 4 SMSPs: 2 warps per SMSP.
// fwd: alpha over emissions 0..511.  bwd: beta over emissions 1023..512 with E^T.
// Z = Mf + Mb + log(sum_i alphaHat_i * betaHat_i).
// Emissions prefetched through an 8-deep register ring (one step's LDGs per
// iteration) so DRAM latency is covered by ~8 compute steps, not 4.
__global__ __launch_bounds__(256, 1)
void CRF_29265907155259_kernel(const float* __restrict__ h_tag,
                               const float* __restrict__ mask,
                               const float* __restrict__ trans,
                               float* __restrict__ out, int B)
{
    __shared__ __align__(16) float vbuf[8][2][KTAGS];   // [warp][pingpong][tag]
    __shared__ float cbuf[8][KTAGS];
    __shared__ double Msh[8];

    const int lane = threadIdx.x & 31;
    const int warp = threadIdx.x >> 5;
    const bool fwd = ((warp & 1) == 0);
    int b = blockIdx.x * 4 + (warp >> 1);
    bool valid = (b < B);
    if (!valid) b = B - 1;                 // clamp (duplicate work) so __syncthreads is safe

    const int tagA = lane;                 // rows 0..31, full j
    const int rowB = 32 + (lane & 15);     // rows 32..47, split j across half-warps
    const bool loB = (lane < 16);
    const int cbB = loB ? 0 : 24;          // j base for B split
    const int pB2 = loB ? 0 : 6;           // ulonglong2 index base for B split

    // ---- E = exp(trans) (fwd) or exp(trans)^T (bwd) rows in registers ----
    unsigned long long EA2[24], EB2[12];
    float rowsumA = 0.f, rowsumBp = 0.f;
    #pragma unroll
    for (int k = 0; k < 24; ++k) {
        int j0 = 2 * k, j1 = 2 * k + 1;
        float a0 = __expf(fwd ? trans[tagA * KTAGS + j0] : trans[j0 * KTAGS + tagA]);
        float a1 = __expf(fwd ? trans[tagA * KTAGS + j1] : trans[j1 * KTAGS + tagA]);
        rowsumA += a0 + a1;
        EA2[k] = pk2(a0, a1);
    }
    #pragma unroll
    for (int k = 0; k < 12; ++k) {
        int j0 = cbB + 2 * k, j1 = cbB + 2 * k + 1;
        float e0 = __expf(fwd ? trans[rowB * KTAGS + j0] : trans[j0 * KTAGS + rowB]);
        float e1 = __expf(fwd ? trans[rowB * KTAGS + j1] : trans[j1 * KTAGS + rowB]);
        rowsumBp += e0 + e1;
        EB2[k] = pk2(e0, e1);
    }
    const float rowsumB = rowsumBp + __shfl_xor_sync(0xffffffffu, rowsumBp, 16);

    const float* eb = h_tag + (size_t)b * TLEN * KTAGS;
    const float* mb = mask + (size_t)b * TLEN;

    float vA, vB;
    double M;

    if (fwd) {
        // ---- special step t = 0 (log domain, exact; exp-domain would underflow) ----
        float m0 = mb[0];
        float e0A = eb[tagA];
        float e0B = eb[rowB];
        float sA = NEGV + __logf(1.0f + rowsumA) + e0A;
        float sB = NEGV + __logf(1.0f + rowsumB) + e0B;
        sA = (m0 != 0.f) ? sA : NEGV;                            // rows 0..31: never STOP
        sB = (m0 != 0.f) ? sB : ((rowB == STOPID) ? 0.f : NEGV);
        float loc = fmaxf(sA, sB);
        #pragma unroll
        for (int o = 16; o; o >>= 1)
            loc = fmaxf(loc, __shfl_xor_sync(0xffffffffu, loc, o));
        M = (double)loc;
        vA = __expf(sA - loc);
        vB = __expf(sB - loc);
    } else {
        // beta_{1023}(i) = exp(trans[STOP, i]); values O(e^4) -> no scaling needed
        vA = __expf(trans[STOPID * KTAGS + tagA]);
        vB = __expf(trans[STOPID * KTAGS + rowB]);
        M = 0.0;
    }

    // step s -> emission index t: fwd t = s (s=1..511); bwd t = 1024-s (s=1..512)
    // ---- 8-deep emit/mask prefetch ring ----
    float nA[8], nB[8], nM[8];
    #pragma unroll
    for (int u = 0; u < 8; ++u) {
        int s = 1 + u;
        int t = fwd ? s : (TLEN - s);
        nA[u] = eb[t * KTAGS + tagA];
        nB[u] = eb[t * KTAGS + rowB];
        nM[u] = mb[t];
    }

    int pp = 0;
    for (int base = 1; base < 513; base += 8) {
        #pragma unroll
        for (int u = 0; u < 8; ++u) {
            int s = base + u;
            if (fwd && s > 511) break;            // fwd: 511 loop steps; bwd: 512

            // consume ring slot u (loaded 8 steps ago), refill for step s+8
            float cAx = nA[u], cBx = nB[u], cMx = nM[u];
            {
                int sp = s + 8;                   // max 520: valid t both directions
                int tp = fwd ? sp : (TLEN - sp);
                nA[u] = eb[tp * KTAGS + tagA];
                nB[u] = eb[tp * KTAGS + rowB];
                nM[u] = mb[tp];
            }

            float eEA = __expf(cAx);
            float eEB = __expf(cBx);

            // fwd stores v, multiplies emission after matvec (alpha' = D E alpha)
            // bwd stores v*exp(e), matvec only (beta' = E^T D beta)
            float wA = fwd ? vA : vA * eEA;
            float wB = fwd ? vB : vB * eEB;
            vbuf[warp][pp][lane] = wA;
            if (loB) vbuf[warp][pp][32 + lane] = wB;
            __syncwarp();

            const ulonglong2* vp = (const ulonglong2*)&vbuf[warp][pp][0];
            unsigned long long aA[4] = {0, 0, 0, 0};
            unsigned long long aB[2] = {0, 0};
            // A rows: full-j dot (broadcast LDS.128)
            #pragma unroll
            for (int k2 = 0; k2 < 12; ++k2) {
                ulonglong2 w = vp[k2];
                fma2(aA[(2 * k2) % 4],     EA2[2 * k2],     w.x);
                fma2(aA[(2 * k2 + 1) % 4], EA2[2 * k2 + 1], w.y);
            }
            // B rows: half-j per half-warp, shfl merge
            #pragma unroll
            for (int k2 = 0; k2 < 6; ++k2) {
                ulonglong2 w = vp[pB2 + k2];
                fma2(aB[0], EB2[2 * k2],     w.x);
                fma2(aB[1], EB2[2 * k2 + 1], w.y);
            }
            add2(aA[0], aA[2]); add2(aA[1], aA[3]); add2(aA[0], aA[1]);
            add2(aB[0], aB[1]);

            float l0, h0;
            upk2(aA[0], l0, h0); float dotA = l0 + h0;
            upk2(aB[0], l0, h0); float pBs = l0 + h0;
            float dotB = pBs + __shfl_xor_sync(0xffffffffu, pBs, 16);

            float rawA = fwd ? dotA * eEA : dotA;
            float rawB = fwd ? dotB * eEB : dotB;
            bool live = (cMx != 0.f);
            vA = live ? rawA : vA;
            vB = live ? rawB : vB;

            // renorm every 4 steps (base = 1 mod 8 -> u==3 / u==7) + fwd tail
            if ((u == 3) || (u == 7) || (fwd && s == 511)) {
                // all v >= 0 -> float max == uint max
                float lmax = fmaxf(vA, vB);
                float mx = __uint_as_float(__reduce_max_sync(0xffffffffu, __float_as_uint(lmax)));
                float r = __fdividef(1.0f, mx);
                vA *= r;
                vB *= r;
                M += (double)__logf(mx);
            }
            pp ^= 1;
        }
    }

    // ---- combine: Z = Mf + Mb + log(sum_i alpha_i * beta_i) ----
    cbuf[warp][lane] = vA;
    if (loB) cbuf[warp][32 + lane] = vB;
    if (lane == 0) Msh[warp] = M;
    __syncthreads();

    if (fwd) {
        float fin = cbuf[warp][lane] * cbuf[warp + 1][lane];
        if (loB) fin += cbuf[warp][32 + lane] * cbuf[warp + 1][32 + lane];
        #pragma unroll
        for (int o = 16; o; o >>= 1)
            fin += __shfl_xor_sync(0xffffffffu, fin, o);
        if (lane == 0 && valid)
            out[b] = (float)(Msh[warp] + Msh[warp + 1] + (double)__logf(fin));
    }
}

extern "C" void kernel_launch(void* const* d_in, const int* in_sizes, int n_in,
                              void* d_out, int out_size) {
    const float* h_tag = (const float*)d_in[0];
    const float* msk   = (const float*)d_in[1];
    const float* trans = (const float*)d_in[2];
    float* out = (float*)d_out;
    int B = in_sizes[0] / (TLEN * KTAGS);
    int blocks = (B + 3) / 4;
    CRF_29265907155259_kernel<<<blocks, 256>>>(h_tag, msk, trans, out, B);
}

// round 12
// speedup vs baseline: 2.3083x; 2.3083x over previous
#include <cuda_runtime.h>

#define KTAGS 48
#define TLEN 1024
#define STOPID 47
#define NEGV (-10000.0f)

__device__ __forceinline__ unsigned long long pk2(float lo, float hi) {
    unsigned long long r;
    asm("mov.b64 %0, {%1, %2};" : "=l"(r) : "f"(lo), "f"(hi));
    return r;
}
__device__ __forceinline__ void upk2(unsigned long long v, float& lo, float& hi) {
    asm("mov.b64 {%0, %1}, %2;" : "=f"(lo), "=f"(hi) : "l"(v));
}
// d = a*b + d  (packed f32x2 -> SASS FFMA2)
__device__ __forceinline__ void fma2(unsigned long long& d, unsigned long long a, unsigned long long b) {
    asm("fma.rn.f32x2 %0, %1, %2, %0;" : "+l"(d) : "l"(a), "l"(b));
}
__device__ __forceinline__ void add2(unsigned long long& d, unsigned long long a) {
    asm("add.rn.f32x2 %0, %0, %1;" : "+l"(d) : "l"(a));
}

// One block = 4 batches, 8 warps. Warp w: batch blk*4 + (w>>1), fwd if (w&1)==0.
// fwd: alpha over emissions 0..511.  bwd: beta over emissions 1023..512 with E^T.
// Z = Mf + Mb + log(sum_i alphaHat_i * betaHat_i).
// Per step: one smem exchange of v; lane owns row `lane` (A, rows 0..31) and
// row 32+(lane&15) (B, rows 32..47, all full-j, duplicated across half-warps;
// only lanes 0..15 store). Renorm every 4 steps by an exact power-of-2 scale
// derived from the REDUX max's exponent bits (no div/log/double on the chain).
__global__ __launch_bounds__(256, 1)
void CRF_29265907155259_kernel(const float* __restrict__ h_tag,
                               const float* __restrict__ mask,
                               const float* __restrict__ trans,
                               float* __restrict__ out, int B)
{
    __shared__ __align__(16) float vbuf[8][2][KTAGS];   // [warp][pingpong][tag]
    __shared__ float cbuf[8][KTAGS];
    __shared__ double Msh[8];

    const int lane = threadIdx.x & 31;
    const int warp = threadIdx.x >> 5;
    const bool fwd = ((warp & 1) == 0);
    int b = blockIdx.x * 4 + (warp >> 1);
    bool valid = (b < B);
    if (!valid) b = B - 1;                 // clamp (duplicate work) so __syncthreads is safe

    const int tagA = lane;                 // rows 0..31
    const int rowB = 32 + (lane & 15);     // rows 32..47 (dup across half-warps)
    const bool loB = (lane < 16);

    // ---- E = exp(trans) (fwd) or exp(trans)^T (bwd) rows in registers ----
    unsigned long long EA2[24], EB2[24];
    float rowsumA = 0.f, rowsumB = 0.f;
    #pragma unroll
    for (int k = 0; k < 24; ++k) {
        int j0 = 2 * k, j1 = 2 * k + 1;
        float a0 = __expf(fwd ? trans[tagA * KTAGS + j0] : trans[j0 * KTAGS + tagA]);
        float a1 = __expf(fwd ? trans[tagA * KTAGS + j1] : trans[j1 * KTAGS + tagA]);
        rowsumA += a0 + a1;
        EA2[k] = pk2(a0, a1);
        float b0 = __expf(fwd ? trans[rowB * KTAGS + j0] : trans[j0 * KTAGS + rowB]);
        float b1 = __expf(fwd ? trans[rowB * KTAGS + j1] : trans[j1 * KTAGS + rowB]);
        rowsumB += b0 + b1;
        EB2[k] = pk2(b0, b1);
    }

    const float* eb = h_tag + (size_t)b * TLEN * KTAGS;
    const float* mb = mask + (size_t)b * TLEN;

    float vA, vB;
    double M0;
    int Mint = 0;

    if (fwd) {
        // ---- special step t = 0 (log domain, exact; exp-domain would underflow) ----
        float m0 = mb[0];
        float e0A = eb[tagA];
        float e0B = eb[rowB];
        float sA = NEGV + __logf(1.0f + rowsumA) + e0A;
        float sB = NEGV + __logf(1.0f + rowsumB) + e0B;
        sA = (m0 != 0.f) ? sA : NEGV;                            // rows 0..31: never STOP
        sB = (m0 != 0.f) ? sB : ((rowB == STOPID) ? 0.f : NEGV);
        float loc = fmaxf(sA, sB);
        #pragma unroll
        for (int o = 16; o; o >>= 1)
            loc = fmaxf(loc, __shfl_xor_sync(0xffffffffu, loc, o));
        M0 = (double)loc;
        vA = __expf(sA - loc);
        vB = __expf(sB - loc);
    } else {
        // beta_{1023}(i) = exp(trans[STOP, i]); values O(e^4) -> no scaling needed
        vA = __expf(trans[STOPID * KTAGS + tagA]);
        vB = __expf(trans[STOPID * KTAGS + rowB]);
        M0 = 0.0;
    }

    // step s -> emission index t: fwd t = s (s=1..511); bwd t = 1024-s (s=1..512)
    // ---- emit/mask prefetch, one 4-step group ahead (proven R8 structure) ----
    float nA[4], nB[4], nM[4];
    #pragma unroll
    for (int u = 0; u < 4; ++u) {
        int s = 1 + u;
        int t = fwd ? s : (TLEN - s);
        nA[u] = eb[t * KTAGS + tagA];
        nB[u] = eb[t * KTAGS + rowB];
        nM[u] = mb[t];
    }

    int pp = 0;
    for (int base = 1; base < 513; base += 4) {
        float cA[4], cB[4], cM[4];
        #pragma unroll
        for (int u = 0; u < 4; ++u) { cA[u] = nA[u]; cB[u] = nB[u]; cM[u] = nM[u]; }
        #pragma unroll
        for (int u = 0; u < 4; ++u) {
            int s = base + 4 + u;                 // max 516; t valid both directions
            int t = fwd ? s : (TLEN - s);
            nA[u] = eb[t * KTAGS + tagA];
            nB[u] = eb[t * KTAGS + rowB];
            nM[u] = mb[t];
        }
        #pragma unroll
        for (int u = 0; u < 4; ++u) {
            int s = base + u;
            if (fwd && s > 511) break;            // fwd: 511 loop steps; bwd: 512

            float eEA = __expf(cA[u]);
            float eEB = __expf(cB[u]);

            // fwd stores v, multiplies emission after matvec (alpha' = D E alpha)
            // bwd stores v*exp(e), matvec only (beta' = E^T D beta)
            float wA = fwd ? vA : vA * eEA;
            float wB = fwd ? vB : vB * eEB;
            vbuf[warp][pp][lane] = wA;
            if (loB) vbuf[warp][pp][32 + lane] = wB;
            __syncwarp();

            // Load all 12 value-pairs once; both row-dots reuse them.
            const ulonglong2* vp = (const ulonglong2*)&vbuf[warp][pp][0];
            ulonglong2 w[12];
            #pragma unroll
            for (int k2 = 0; k2 < 12; ++k2) w[k2] = vp[k2];

            unsigned long long aA[4] = {0, 0, 0, 0};
            unsigned long long aB[4] = {0, 0, 0, 0};
            #pragma unroll
            for (int k2 = 0; k2 < 12; ++k2) {
                fma2(aA[(2 * k2) % 4],     EA2[2 * k2],     w[k2].x);
                fma2(aA[(2 * k2 + 1) % 4], EA2[2 * k2 + 1], w[k2].y);
                fma2(aB[(2 * k2) % 4],     EB2[2 * k2],     w[k2].x);
                fma2(aB[(2 * k2 + 1) % 4], EB2[2 * k2 + 1], w[k2].y);
            }
            add2(aA[0], aA[2]); add2(aA[1], aA[3]); add2(aA[0], aA[1]);
            add2(aB[0], aB[2]); add2(aB[1], aB[3]); add2(aB[0], aB[1]);

            float l0, h0;
            upk2(aA[0], l0, h0); float dotA = l0 + h0;
            upk2(aB[0], l0, h0); float dotB = l0 + h0;

            float rawA = fwd ? dotA * eEA : dotA;
            float rawB = fwd ? dotB * eEB : dotB;
            bool live = (cM[u] != 0.f);
            vA = live ? rawA : vA;
            vB = live ? rawB : vB;

            if ((u == 3) || (fwd && s == 511)) {
                // all v >= 0 -> float max == uint max; scale by exact power of 2
                float lmax = fmaxf(vA, vB);
                unsigned mxb = __reduce_max_sync(0xffffffffu, __float_as_uint(lmax));
                int ebx = (int)(mxb >> 23);                       // biased exponent of max
                float r = __uint_as_float((unsigned)(254 - ebx) << 23);  // 2^(127-eb)
                vA *= r;
                vB *= r;
                Mint += ebx - 127;
            }
            pp ^= 1;
        }
    }

    // ---- combine: Z = Mf + Mb + log(sum_i alpha_i * beta_i) ----
    cbuf[warp][lane] = vA;
    if (loB) cbuf[warp][32 + lane] = vB;
    if (lane == 0) Msh[warp] = M0 + (double)Mint * 0.6931471805599453;
    __syncthreads();

    if (fwd) {
        float fin = cbuf[warp][lane] * cbuf[warp + 1][lane];
        if (loB) fin += cbuf[warp][32 + lane] * cbuf[warp + 1][32 + lane];
        #pragma unroll
        for (int o = 16; o; o >>= 1)
            fin += __shfl_xor_sync(0xffffffffu, fin, o);
        if (lane == 0 && valid)
            out[b] = (float)(Msh[warp] + Msh[warp + 1] + (double)__logf(fin));
    }
}

extern "C" void kernel_launch(void* const* d_in, const int* in_sizes, int n_in,
                              void* d_out, int out_size) {
    const float* h_tag = (const float*)d_in[0];
    const float* msk   = (const float*)d_in[1];
    const float* trans = (const float*)d_in[2];
    float* out = (float*)d_out;
    int B = in_sizes[0] / (TLEN * KTAGS);
    int blocks = (B + 3) / 4;
    CRF_29265907155259_kernel<<<blocks, 256>>>(h_tag, msk, trans, out, B);
}

// round 14
// speedup vs baseline: 3.0158x; 1.3065x over previous
#include <cuda_runtime.h>

#define KTAGS 48
#define TLEN 1024
#define STOPID 47
#define NEGV (-10000.0f)

__device__ __forceinline__ unsigned long long pk2(float lo, float hi) {
    unsigned long long r;
    asm("mov.b64 %0, {%1, %2};" : "=l"(r) : "f"(lo), "f"(hi));
    return r;
}
__device__ __forceinline__ void upk2(unsigned long long v, float& lo, float& hi) {
    asm("mov.b64 {%0, %1}, %2;" : "=f"(lo), "=f"(hi) : "l"(v));
}
// d = a*b + d  (packed f32x2 -> SASS FFMA2)
__device__ __forceinline__ void fma2(unsigned long long& d, unsigned long long a, unsigned long long b) {
    asm("fma.rn.f32x2 %0, %1, %2, %0;" : "+l"(d) : "l"(a), "l"(b));
}
__device__ __forceinline__ void add2(unsigned long long& d, unsigned long long a) {
    asm("add.rn.f32x2 %0, %0, %1;" : "+l"(d) : "l"(a));
}

// Renorm: exact power-of-2 scale from the warp-max exponent. All v >= 0.
__device__ __forceinline__ void renorm(float& vA, float& vB, int& Mint) {
    float lmax = fmaxf(vA, vB);
    unsigned mxb = __reduce_max_sync(0xffffffffu, __float_as_uint(lmax));
    int ebx = (int)(mxb >> 23);                              // biased exponent of max
    float r = __uint_as_float((unsigned)(254 - ebx) << 23);  // 2^(127-eb)
    vA *= r;
    vB *= r;
    Mint += ebx - 127;
}

// One recurrence chain, direction compile-time specialized.
// FWD: alpha' = D_t E alpha  over emissions s=1..511 (t=s).
// !FWD: beta' = E^T D_t beta over emissions s=1..512 (t=1024-s).
// Renorm every 8 steps (worst-case 8-step growth ~e^62 < fp32 max e^88),
// plus a forced renorm after the loop so the alpha*beta combine can't overflow.
template <bool FWD>
__device__ __forceinline__ void run_chain(
    const float* __restrict__ eb, const float* __restrict__ mb,
    const unsigned long long* EA2, const unsigned long long* EB2,
    float& vA, float& vB, int& Mint,
    float* __restrict__ vbuf0, float* __restrict__ vbuf1,
    int lane, bool loB)
{
    const int rB = 32 + (lane & 15);
    float nA[4], nB[4], nM[4];
    #pragma unroll
    for (int u = 0; u < 4; ++u) {
        int s = 1 + u;
        int t = FWD ? s : (TLEN - s);
        nA[u] = eb[t * KTAGS + lane];
        nB[u] = eb[t * KTAGS + rB];
        nM[u] = mb[t];
    }

    float* vcur = vbuf0;
    float* vnxt = vbuf1;
    for (int base = 1; base < 513; base += 4) {
        // hoist the group's exps off the per-step chain (MUFU lat 16 + mul
        // otherwise gates the bwd store at every step head)
        float eA[4], eB[4], cM[4];
        #pragma unroll
        for (int u = 0; u < 4; ++u) {
            eA[u] = __expf(nA[u]);
            eB[u] = __expf(nB[u]);
            cM[u] = nM[u];
        }
        #pragma unroll
        for (int u = 0; u < 4; ++u) {
            int s = base + 4 + u;                 // max 516; t valid both directions
            int t = FWD ? s : (TLEN - s);
            nA[u] = eb[t * KTAGS + lane];
            nB[u] = eb[t * KTAGS + rB];
            nM[u] = mb[t];
        }
        #pragma unroll
        for (int u = 0; u < 4; ++u) {
            int s = base + u;
            if (FWD && s > 511) break;            // fwd: 511 loop steps; bwd: 512

            // fwd stores v, multiplies emission after matvec (alpha' = D E alpha)
            // bwd stores v*exp(e), matvec only (beta' = E^T D beta)
            float wA = FWD ? vA : vA * eA[u];
            float wB = FWD ? vB : vB * eB[u];
            vcur[lane] = wA;
            if (loB) vcur[32 + lane] = wB;
            __syncwarp();

            // Load all 12 value-pairs once; both row-dots reuse them.
            const ulonglong2* vp = (const ulonglong2*)vcur;
            ulonglong2 w[12];
            #pragma unroll
            for (int k2 = 0; k2 < 12; ++k2) w[k2] = vp[k2];

            unsigned long long aA[4] = {0, 0, 0, 0};
            unsigned long long aB[4] = {0, 0, 0, 0};
            #pragma unroll
            for (int k2 = 0; k2 < 12; ++k2) {
                fma2(aA[(2 * k2) % 4],     EA2[2 * k2],     w[k2].x);
                fma2(aA[(2 * k2 + 1) % 4], EA2[2 * k2 + 1], w[k2].y);
                fma2(aB[(2 * k2) % 4],     EB2[2 * k2],     w[k2].x);
                fma2(aB[(2 * k2 + 1) % 4], EB2[2 * k2 + 1], w[k2].y);
            }
            add2(aA[0], aA[2]); add2(aA[1], aA[3]); add2(aA[0], aA[1]);
            add2(aB[0], aB[2]); add2(aB[1], aB[3]); add2(aB[0], aB[1]);

            float l0, h0;
            upk2(aA[0], l0, h0); float dotA = l0 + h0;
            upk2(aB[0], l0, h0); float dotB = l0 + h0;

            float rawA = FWD ? dotA * eA[u] : dotA;
            float rawB = FWD ? dotB * eB[u] : dotB;
            bool live = (cM[u] != 0.f);
            vA = live ? rawA : vA;
            vB = live ? rawB : vB;

            // renorm every 8 steps: groups base=5,13,... at u==3 -> s=8,16,...
            if ((u == 3) && ((base & 4) != 0))
                renorm(vA, vB, Mint);

            float* tp = vcur; vcur = vnxt; vnxt = tp;
        }
    }
    renorm(vA, vB, Mint);                         // bound v before alpha*beta combine
}

// One block = 4 batches, 8 warps. Warp w: batch blk*4 + (w>>1), fwd if (w&1)==0.
// Z = Mf + Mb + log(sum_i alphaHat_i * betaHat_i).
__global__ __launch_bounds__(256, 1)
void CRF_29265907155259_kernel(const float* __restrict__ h_tag,
                               const float* __restrict__ mask,
                               const float* __restrict__ trans,
                               float* __restrict__ out, int B)
{
    __shared__ __align__(16) float vbuf[8][2][KTAGS];   // [warp][pingpong][tag]
    __shared__ float cbuf[8][KTAGS];
    __shared__ double Msh[8];

    const int lane = threadIdx.x & 31;
    const int warp = threadIdx.x >> 5;
    const bool fwd = ((warp & 1) == 0);
    int b = blockIdx.x * 4 + (warp >> 1);
    bool valid = (b < B);
    if (!valid) b = B - 1;                 // clamp (duplicate work) so __syncthreads is safe

    const int tagA = lane;                 // rows 0..31
    const int rowB = 32 + (lane & 15);     // rows 32..47 (dup across half-warps)
    const bool loB = (lane < 16);

    // ---- E = exp(trans) (fwd) or exp(trans)^T (bwd) rows in registers ----
    unsigned long long EA2[24], EB2[24];
    float rowsumA = 0.f, rowsumB = 0.f;
    #pragma unroll
    for (int k = 0; k < 24; ++k) {
        int j0 = 2 * k, j1 = 2 * k + 1;
        float a0 = __expf(fwd ? trans[tagA * KTAGS + j0] : trans[j0 * KTAGS + tagA]);
        float a1 = __expf(fwd ? trans[tagA * KTAGS + j1] : trans[j1 * KTAGS + tagA]);
        rowsumA += a0 + a1;
        EA2[k] = pk2(a0, a1);
        float b0 = __expf(fwd ? trans[rowB * KTAGS + j0] : trans[j0 * KTAGS + rowB]);
        float b1 = __expf(fwd ? trans[rowB * KTAGS + j1] : trans[j1 * KTAGS + rowB]);
        rowsumB += b0 + b1;
        EB2[k] = pk2(b0, b1);
    }

    const float* eb = h_tag + (size_t)b * TLEN * KTAGS;
    const float* mb = mask + (size_t)b * TLEN;

    float vA, vB;
    double M0;
    int Mint = 0;

    if (fwd) {
        // ---- special step t = 0 (log domain, exact; exp-domain would underflow) ----
        float m0 = mb[0];
        float e0A = eb[tagA];
        float e0B = eb[rowB];
        float sA = NEGV + __logf(1.0f + rowsumA) + e0A;
        float sB = NEGV + __logf(1.0f + rowsumB) + e0B;
        sA = (m0 != 0.f) ? sA : NEGV;                            // rows 0..31: never STOP
        sB = (m0 != 0.f) ? sB : ((rowB == STOPID) ? 0.f : NEGV);
        float loc = fmaxf(sA, sB);
        #pragma unroll
        for (int o = 16; o; o >>= 1)
            loc = fmaxf(loc, __shfl_xor_sync(0xffffffffu, loc, o));
        M0 = (double)loc;
        vA = __expf(sA - loc);
        vB = __expf(sB - loc);
    } else {
        // beta_{1023}(i) = exp(trans[STOP, i]); values O(e^4) -> no scaling needed
        vA = __expf(trans[STOPID * KTAGS + tagA]);
        vB = __expf(trans[STOPID * KTAGS + rowB]);
        M0 = 0.0;
    }

    if (fwd)
        run_chain<true >(eb, mb, EA2, EB2, vA, vB, Mint,
                         &vbuf[warp][0][0], &vbuf[warp][1][0], lane, loB);
    else
        run_chain<false>(eb, mb, EA2, EB2, vA, vB, Mint,
                         &vbuf[warp][0][0], &vbuf[warp][1][0], lane, loB);

    // ---- combine: Z = Mf + Mb + log(sum_i alpha_i * beta_i) ----
    cbuf[warp][lane] = vA;
    if (loB) cbuf[warp][32 + lane] = vB;
    if (lane == 0) Msh[warp] = M0 + (double)Mint * 0.6931471805599453;
    __syncthreads();

    if (fwd) {
        float fin = cbuf[warp][lane] * cbuf[warp + 1][lane];
        if (loB) fin += cbuf[warp][32 + lane] * cbuf[warp + 1][32 + lane];
        #pragma unroll
        for (int o = 16; o; o >>= 1)
            fin += __shfl_xor_sync(0xffffffffu, fin, o);
        if (lane == 0 && valid)
            out[b] = (float)(Msh[warp] + Msh[warp + 1] + (double)__logf(fin));
    }
}

extern "C" void kernel_launch(void* const* d_in, const int* in_sizes, int n_in,
                              void* d_out, int out_size) {
    const float* h_tag = (const float*)d_in[0];
    const float* msk   = (const float*)d_in[1];
    const float* trans = (const float*)d_in[2];
    float* out = (float*)d_out;
    int B = in_sizes[0] / (TLEN * KTAGS);
    int blocks = (B + 3) / 4;
    CRF_29265907155259_kernel<<<blocks, 256>>>(h_tag, msk, trans, out, B);
}